// round 10
// baseline (speedup 1.0000x reference)
#include <cuda_runtime.h>
#include <cuda_bf16.h>
#include <math.h>

#define EDIM 8192      // N == E == 8192
#define TM   128       // rows per CTA
#define TK   64        // K-chunk
#define NTH  384
#define NCHUNK (EDIM / TK)

// ---- shared memory layout (bytes) ----
#define OFF_A    0          // 2 x 32 KB adjacency staging [64 k][128 i] int32
#define OFF_P    65536      // 2 x (Ph 16KB + Pl 16KB) = 64 KB
#define OFF_X    131072     // 4 x 16 KB (Xh 8KB + Xl 8KB) [64 d][64 k] bf16
#define OFF_BV   196608     // 2 x 1 KB packed col triples float4[64]
#define OFF_ZC   198656     // 1 KB z[128], cnt[128]
#define OFF_W    199680     // 16 KB weight matrix (persistent)
#define SMEM_BYTES 216064
// epilogue reuse of dead A+P region
#define OFF_M    0
#define MSTRIDE  65

// named barrier ids
#define BFULL0 1
#define BFULL1 2
#define BFREE0 3
#define BFREE1 4
#define BPROD  5

// ---- device scratch ----
__device__ __align__(16) float g_rA  [2][EDIM];
__device__ __align__(16) float g_rEA [2][EDIM];
__device__ __align__(16) float g_rEA2[2][EDIM];
__device__ __align__(16) float4 g_cPack[2 * EDIM];          // {b, eb, eb2, 0}
__device__ __align__(16) __nv_bfloat16 g_XhT[2][64 * EDIM]; // X^T hi split [d][k]
__device__ __align__(16) __nv_bfloat16 g_XlT[2][64 * EDIM]; // X^T lo split

// ---- PTX helpers ----
__device__ __forceinline__ unsigned smem_u32(const void* p) {
  unsigned a;
  asm("{ .reg .u64 t; cvta.to.shared.u64 t, %1; cvt.u32.u64 %0, t; }" : "=r"(a) : "l"(p));
  return a;
}
__device__ __forceinline__ void cp16(void* dst, const void* src) {
  unsigned sa = smem_u32(dst);
  asm volatile("cp.async.cg.shared.global [%0], [%1], 16;" :: "r"(sa), "l"(src) : "memory");
}
__device__ __forceinline__ void cp_commit() { asm volatile("cp.async.commit_group;" ::: "memory"); }
__device__ __forceinline__ void cp_wait1()  { asm volatile("cp.async.wait_group 1;" ::: "memory"); }

__device__ __forceinline__ void bar_sync(int id, int cnt) {
  asm volatile("bar.sync %0, %1;" :: "r"(id), "r"(cnt) : "memory");
}
__device__ __forceinline__ void bar_arrive(int id, int cnt) {
  asm volatile("bar.arrive %0, %1;" :: "r"(id), "r"(cnt) : "memory");
}

__device__ __forceinline__ void ldsm4(unsigned& r0, unsigned& r1, unsigned& r2, unsigned& r3,
                                      unsigned addr) {
  asm volatile("ldmatrix.sync.aligned.m8n8.x4.shared.b16 {%0,%1,%2,%3}, [%4];"
               : "=r"(r0), "=r"(r1), "=r"(r2), "=r"(r3) : "r"(addr));
}
__device__ __forceinline__ void mma16816(float* c, const unsigned* a, unsigned b0, unsigned b1) {
  asm volatile("mma.sync.aligned.m16n8k16.row.col.f32.bf16.bf16.f32 "
               "{%0,%1,%2,%3}, {%4,%5,%6,%7}, {%8,%9}, {%0,%1,%2,%3};"
               : "+f"(c[0]), "+f"(c[1]), "+f"(c[2]), "+f"(c[3])
               : "r"(a[0]), "r"(a[1]), "r"(a[2]), "r"(a[3]), "r"(b0), "r"(b1));
}

// ---------------------------------------------------------------------------
// Prep: q = W@p folds, per-index score scalars + exps, packed col triples,
// and bf16-split TRANSPOSED feature matrices XhT/XlT.
// ---------------------------------------------------------------------------
__global__ void prep_kernel(const float* __restrict__ nf, const float* __restrict__ ef,
                            const float* __restrict__ Wn, const float* __restrict__ We,
                            const float* __restrict__ pn, const float* __restrict__ pe) {
  __shared__ float sq[256];
  __shared__ float tN[64 * 65];
  __shared__ float tE[64 * 65];
  int t = threadIdx.x;
  int i0 = blockIdx.x * 64;
  {
    int v = t >> 6, d = t & 63;
    const float* W = (v == 1) ? Wn : We;
    const float* p = (v == 0) ? pn : (v == 1) ? (pn + 64) : (v == 2) ? pe : (pe + 64);
    float s = 0.f;
    #pragma unroll
    for (int e = 0; e < 64; e++) s += W[d * 64 + e] * p[e];
    sq[t] = s;
  }
  for (int u = t; u < 1024; u += 256) {
    int r = u >> 4, c = (u & 15) * 4;
    float4 v4 = *(const float4*)(nf + (size_t)(i0 + r) * 64 + c);
    tN[r*65+c] = v4.x; tN[r*65+c+1] = v4.y; tN[r*65+c+2] = v4.z; tN[r*65+c+3] = v4.w;
    float4 e4 = *(const float4*)(ef + (size_t)(i0 + r) * 64 + c);
    tE[r*65+c] = e4.x; tE[r*65+c+1] = e4.y; tE[r*65+c+2] = e4.z; tE[r*65+c+3] = e4.w;
  }
  __syncthreads();
  {
    int v = t & 3, r = t >> 2;
    const float* tl = (v == 1) ? tN : tE;
    const float* q = sq + v * 64;
    float s = 0.f;
    #pragma unroll
    for (int e = 0; e < 64; e++) s += tl[r * 65 + e] * q[e];
    int i = i0 + r;
    float es = expf(s), es2 = expf(0.01f * s);
    if (v == 0)      { g_rA[0][i] = s; g_rEA[0][i] = es; g_rEA2[0][i] = es2; }
    else if (v == 2) { g_rA[1][i] = s; g_rEA[1][i] = es; g_rEA2[1][i] = es2; }
    else if (v == 1) { g_cPack[i]        = make_float4(s, es, es2, 0.f); }
    else             { g_cPack[EDIM + i] = make_float4(s, es, es2, 0.f); }
  }
  for (int u = t; u < 4096; u += 256) {
    int d = u >> 6, ii = u & 63;
    size_t o = (size_t)d * EDIM + i0 + ii;
    float x = tN[ii * 65 + d];
    __nv_bfloat16 h = __float2bfloat16_rn(x);
    g_XhT[0][o] = h;
    g_XlT[0][o] = __float2bfloat16_rn(x - __bfloat162float(h));
    float y = tE[ii * 65 + d];
    __nv_bfloat16 g = __float2bfloat16_rn(y);
    g_XhT[1][o] = g;
    g_XlT[1][o] = __float2bfloat16_rn(y - __bfloat162float(g));
  }
}

// ---- producer chunk loader (128 threads) ----
__device__ __forceinline__ void p_load(char* sm, int b, int ch,
    const int* __restrict__ adjG, const float4* __restrict__ cPak,
    const __nv_bfloat16* __restrict__ XhT, const __nv_bfloat16* __restrict__ XlT,
    int i0, int tp) {
  char* sA = sm + OFF_A + b * 32768;
  int k0 = ch * TK;
  const char* adjB = (const char*)adjG;
  #pragma unroll
  for (int u = tp; u < 2048; u += 128) {
    int kk = u >> 5, o = u & 31;
    cp16(sA + (size_t)kk * 512 + o * 16,
         adjB + (((size_t)(k0 + kk) * EDIM + i0) << 2) + (size_t)o * 16);
  }
  char* sXh = sm + OFF_X + (ch & 3) * 16384;
  char* sXl = sXh + 8192;
  #pragma unroll
  for (int u = tp; u < 512; u += 128) {
    int d = u >> 3, o = (u & 7) * 16;
    unsigned off = d * 128 + o;
    unsigned sw = off ^ ((off >> 3) & 0x70);
    cp16(sXh + sw, (const char*)(XhT + (size_t)d * EDIM + k0) + o);
    cp16(sXl + sw, (const char*)(XlT + (size_t)d * EDIM + k0) + o);
  }
  if (tp < 64) cp16(sm + OFF_BV + b * 1024 + tp * 16, (const char*)(cPak + k0 + tp));
}

// ---------------------------------------------------------------------------
// Main: warp-specialized, 12 warps. Warps 8-11 (producers) build bf16-split
// P tiles + Z/cnt + drive cp.async. Warps 0-7 (consumers) each own an
// M=32 x N=32 quadrant of D += Ph@Xh^T + Ph@Xl^T + Pl@Xh^T via mma.sync.
// 3 warps/SMSP (2 consumers + 1 producer) for latency hiding.
// ---------------------------------------------------------------------------
__global__ void __launch_bounds__(NTH, 1)
agg_kernel(const int* __restrict__ e2e, const int* __restrict__ n2e,
           const float* __restrict__ Wn, const float* __restrict__ We,
           float* __restrict__ out) {
  extern __shared__ char sm[];
  const int side = blockIdx.z;
  const int*   adjG = side ? e2e : n2e;
  const float* W    = side ? We  : Wn;
  const __nv_bfloat16* XhT = g_XhT[side];
  const __nv_bfloat16* XlT = g_XlT[side];
  const float4* cPak = g_cPack + side * EDIM;
  const int i0 = blockIdx.x * TM;
  const int t  = threadIdx.x;
  const int wid = t >> 5, lane = t & 31;
  const unsigned smb = smem_u32(sm);

  float* sZC = (float*)(sm + OFF_ZC);
  float* sW  = (float*)(sm + OFF_W);

  if (t >= 256) {
    // ================= PRODUCERS (warps 8-11) =================
    const int tp = t - 256;
    const int i  = tp;
    const float a_i   = g_rA  [side][i0 + i];
    const float ea_i  = g_rEA [side][i0 + i];
    const float ea2_i = g_rEA2[side][i0 + i];
    const int sx = (i & 7) << 4;
    float zacc = 0.f, cacc = 0.f;

    p_load(sm, 0, 0, adjG, cPak, XhT, XlT, i0, tp); cp_commit();
    p_load(sm, 1, 1, adjG, cPak, XhT, XlT, i0, tp); cp_commit();

    for (int ch = 0; ch < NCHUNK; ch++) {
      const int b = ch & 1;
      cp_wait1();                       // group for chunk ch complete
      bar_sync(BPROD, 128);             // all producer slices visible
      if (ch >= 2) bar_sync(b ? BFREE1 : BFREE0, NTH);   // P[b] free

      const int*    sAdj = (const int*)   (sm + OFF_A  + b * 32768);
      const float4* sBV  = (const float4*)(sm + OFF_BV + b * 1024);
      char* phB = sm + OFF_P + b * 32768 + i * 128;
      char* plB = phB + 16384;
      #pragma unroll
      for (int g = 0; g < 8; g++) {
        unsigned ph4[4], pl4[4];
        #pragma unroll
        for (int jj = 0; jj < 4; jj++) {
          int k = g * 8 + jj * 2;
          float fm0 = (float)sAdj[k * TM + i];
          float fm1 = (float)sAdj[(k + 1) * TM + i];
          float4 b0 = sBV[k], b1 = sBV[k + 1];
          float s0 = (a_i + b0.x >= 0.f) ? ea_i * b0.y : ea2_i * b0.z;
          float s1 = (a_i + b1.x >= 0.f) ? ea_i * b1.y : ea2_i * b1.z;
          float w0 = fm0 * s0;
          float w1 = fm1 * s1;
          zacc += w0; zacc += w1;
          cacc += fm0; cacc += fm1;
          unsigned ph;
          asm("cvt.rn.bf16x2.f32 %0, %1, %2;" : "=r"(ph) : "f"(w1), "f"(w0));
          float h0 = __uint_as_float(ph << 16);
          float h1 = __uint_as_float(ph & 0xffff0000u);
          unsigned pl;
          asm("cvt.rn.bf16x2.f32 %0, %1, %2;" : "=r"(pl) : "f"(w1 - h1), "f"(w0 - h0));
          ph4[jj] = ph; pl4[jj] = pl;
        }
        int off = (g * 16) ^ sx;
        *(uint4*)(phB + off) = make_uint4(ph4[0], ph4[1], ph4[2], ph4[3]);
        *(uint4*)(plB + off) = make_uint4(pl4[0], pl4[1], pl4[2], pl4[3]);
      }
      bar_arrive(b ? BFULL1 : BFULL0, NTH);
      bar_sync(BPROD, 128);             // A[b]/BV[b] fully consumed by producers
      if (ch + 2 < NCHUNK)
        p_load(sm, b, ch + 2, adjG, cPak, XhT, XlT, i0, tp);
      cp_commit();                      // always one group per iteration
    }
    sZC[i]       = zacc;
    sZC[128 + i] = cacc;

    __syncthreads();                    // join epilogue
    __syncthreads();
  } else {
    // ================= CONSUMERS (warps 0-7) =================
    for (int u = t; u < 1024; u += 256)
      ((float4*)sW)[u] = ((const float4*)W)[u];

    const int mG = wid & 3, nG = wid >> 2;
    const unsigned mBase = (unsigned)(mG * 32 + (lane & 15)) * 128;
    const unsigned axor  = (lane & 7) << 4;
    const unsigned aCol  = (lane >> 4) << 4;
    unsigned dBase[2];
    {
      int dRow = ((lane >> 4) << 3) + (lane & 7);
      #pragma unroll
      for (int np = 0; np < 2; np++)
        dBase[np] = (unsigned)(nG * 32 + np * 16 + dRow) * 128;
    }
    const unsigned bCol = ((lane >> 3) & 1) << 4;

    float acc[2][4][4];
    #pragma unroll
    for (int mt = 0; mt < 2; mt++)
      #pragma unroll
      for (int j = 0; j < 4; j++)
        #pragma unroll
        for (int q = 0; q < 4; q++) acc[mt][j][q] = 0.f;

    for (int ch = 0; ch < NCHUNK; ch++) {
      const int b = ch & 1;
      bar_sync(b ? BFULL1 : BFULL0, NTH);
      const unsigned pPh = smb + OFF_P + b * 32768;
      const unsigned pPl = pPh + 16384;
      const unsigned pXh = smb + OFF_X + (ch & 3) * 16384;
      const unsigned pXl = pXh + 8192;
      #pragma unroll
      for (int ks = 0; ks < 4; ks++) {
        unsigned ah0[4], ah1[4], al0[4], al1[4];
        unsigned aOff = ((unsigned)(ks * 32) + aCol) ^ axor;
        ldsm4(ah0[0], ah0[1], ah0[2], ah0[3], pPh + mBase + aOff);
        ldsm4(ah1[0], ah1[1], ah1[2], ah1[3], pPh + mBase + 2048 + aOff);
        ldsm4(al0[0], al0[1], al0[2], al0[3], pPl + mBase + aOff);
        ldsm4(al1[0], al1[1], al1[2], al1[3], pPl + mBase + 2048 + aOff);
        unsigned bOff = ((unsigned)(ks * 32) + bCol) ^ axor;
        #pragma unroll
        for (int np = 0; np < 2; np++) {
          unsigned bh[4], bl[4];
          ldsm4(bh[0], bh[1], bh[2], bh[3], pXh + dBase[np] + bOff);
          ldsm4(bl[0], bl[1], bl[2], bl[3], pXl + dBase[np] + bOff);
          mma16816(acc[0][np*2],   ah0, bh[0], bh[1]);
          mma16816(acc[0][np*2+1], ah0, bh[2], bh[3]);
          mma16816(acc[1][np*2],   ah1, bh[0], bh[1]);
          mma16816(acc[1][np*2+1], ah1, bh[2], bh[3]);
          mma16816(acc[0][np*2],   ah0, bl[0], bl[1]);
          mma16816(acc[0][np*2+1], ah0, bl[2], bl[3]);
          mma16816(acc[1][np*2],   ah1, bl[0], bl[1]);
          mma16816(acc[1][np*2+1], ah1, bl[2], bl[3]);
          mma16816(acc[0][np*2],   al0, bh[0], bh[1]);
          mma16816(acc[0][np*2+1], al0, bh[2], bh[3]);
          mma16816(acc[1][np*2],   al1, bh[0], bh[1]);
          mma16816(acc[1][np*2+1], al1, bh[2], bh[3]);
        }
      }
      bar_arrive(b ? BFREE1 : BFREE0, NTH);
    }

    __syncthreads();   // producers wrote sZC; A/P now dead

    // ---- epilogue: scatter normalized means into sM (disjoint regions) ----
    float* sM = (float*)(sm + OFF_M);
    #pragma unroll
    for (int mt = 0; mt < 2; mt++) {
      int r0e = mG * 32 + mt * 16 + (lane >> 2);
      int r1e = r0e + 8;
      float inv0 = 1.f / (sZC[r0e] * sZC[128 + r0e]);
      float inv1 = 1.f / (sZC[r1e] * sZC[128 + r1e]);
      #pragma unroll
      for (int j = 0; j < 4; j++) {
        int c = nG * 32 + j * 8 + (lane & 3) * 2;
        sM[r0e * MSTRIDE + c]     = acc[mt][j][0] * inv0;
        sM[r0e * MSTRIDE + c + 1] = acc[mt][j][1] * inv0;
        sM[r1e * MSTRIDE + c]     = acc[mt][j][2] * inv1;
        sM[r1e * MSTRIDE + c + 1] = acc[mt][j][3] * inv1;
      }
    }
    __syncthreads();
  }

  // ---- projection through W + leaky + store (first 256 threads) ----
  if (t < 256) {
    float* sM = (float*)(sm + OFF_M);
    const int tx = t & 7, ty = t >> 3;
    const int r0 = ty * 4, c0 = tx * 8;
    float o[4][8] = {};
    #pragma unroll 8
    for (int k = 0; k < 64; k++) {
      float mr[4];
      #pragma unroll
      for (int rr = 0; rr < 4; rr++) mr[rr] = sM[(r0 + rr) * MSTRIDE + k];
      float4 wa = *(const float4*)(sW + k * 64 + c0);
      float4 wb = *(const float4*)(sW + k * 64 + c0 + 4);
      float wv[8] = {wa.x, wa.y, wa.z, wa.w, wb.x, wb.y, wb.z, wb.w};
      #pragma unroll
      for (int rr = 0; rr < 4; rr++)
        #pragma unroll
        for (int cc = 0; cc < 8; cc++)
          o[rr][cc] = fmaf(mr[rr], wv[cc], o[rr][cc]);
    }
    #pragma unroll
    for (int rr = 0; rr < 4; rr++) {
      float v[8];
      #pragma unroll
      for (int cc = 0; cc < 8; cc++) {
        float x = o[rr][cc];
        v[cc] = (x >= 0.f) ? x : 0.01f * x;
      }
      float* op = out + (size_t)(i0 + r0 + rr) * 128 + side * 64 + c0;
      *(float4*)(op)     = make_float4(v[0], v[1], v[2], v[3]);
      *(float4*)(op + 4) = make_float4(v[4], v[5], v[6], v[7]);
    }
  }
}

// ---------------------------------------------------------------------------
extern "C" void kernel_launch(void* const* d_in, const int* in_sizes, int n_in,
                              void* d_out, int out_size) {
  const float* nf  = (const float*)d_in[0];
  const float* ef  = (const float*)d_in[1];
  const int*   e2e = (const int*)  d_in[2];
  const int*   n2e = (const int*)  d_in[3];
  const float* Wn  = (const float*)d_in[4];
  const float* We  = (const float*)d_in[5];
  const float* pn  = (const float*)d_in[6];
  const float* pe  = (const float*)d_in[7];
  float* out = (float*)d_out;

  cudaFuncSetAttribute(agg_kernel, cudaFuncAttributeMaxDynamicSharedMemorySize, SMEM_BYTES);

  prep_kernel<<<EDIM / 64, 256>>>(nf, ef, Wn, We, pn, pe);
  dim3 grid(EDIM / TM, 1, 2);
  agg_kernel<<<grid, NTH, SMEM_BYTES>>>(e2e, n2e, Wn, We, out);
}